// round 15
// baseline (speedup 1.0000x reference)
#include <cuda_runtime.h>

#define DD   256
#define NN   8192
#define EE   8191
#define ALPHA 0.2f
#define GRID 128

// ---------------- scratch (allocation-free __device__ globals, zero-init) -------
__device__ float g_w12[2 * DD];
__device__ float g_p[NN];
__device__ float g_q[NN];
// per-output-row gather tables: out_row r = lrelu((cA*x[sA] + cB*x[sB]) @ W^T)
__device__ float g_cA[NN];
__device__ float g_cB[NN];
__device__ int   g_sA[NN];
__device__ int   g_sB[NN];
__device__ unsigned g_b1, g_b2, g_b3, g_br;   // self-resetting each call

__device__ __forceinline__ unsigned f2tf(float f) {
    unsigned r; asm("cvt.rna.tf32.f32 %0, %1;" : "=r"(r) : "f"(f)); return r;
}
__device__ __forceinline__ float tfbits(float f) { return __uint_as_float(f2tf(f)); }
__device__ __forceinline__ float lrelu(float v) { return v > 0.f ? v : ALPHA * v; }
__device__ __forceinline__ unsigned su32(const void* p) {
    return (unsigned)__cvta_generic_to_shared(p);
}
__device__ __forceinline__ float dot4(float4 a, float4 b) {
    return a.x * b.x + a.y * b.y + a.z * b.z + a.w * b.w;
}
__device__ __forceinline__ void gridbar(unsigned* ctr) {
    __syncthreads();
    if (threadIdx.x == 0) {
        __threadfence();
        atomicAdd(ctr, 1u);
        while (*(volatile unsigned*)ctr < GRID) __nanosleep(32);
        __threadfence();
    }
    __syncthreads();
}

#define TSTG (128 * 36)

__global__ __launch_bounds__(512, 1) void k_fused(
    const float* __restrict__ x, const float* __restrict__ W,
    const float* __restrict__ a,
    const int* __restrict__ dep, const int* __restrict__ gov,
    float* __restrict__ out)
{
    extern __shared__ float sm[];
    int tid = threadIdx.x;
    int blk = blockIdx.x;
    int wid = tid >> 5, lane = tid & 31;

    // ================= phase 0: w12 on blocks 0..15 =================
    if (blk < 16) {
        float* p1 = sm;            // [32][16]
        float* p2 = sm + 512;
        int l = tid & 15, g = tid >> 4;      // col-in-slice, j-group (0..31)
        int col = blk * 16 + l;
        int j0 = g * 8;
        float a1 = 0.f, a2 = 0.f;
#pragma unroll
        for (int i = 0; i < 8; i++) {
            float wv = W[(j0 + i) * DD + col];
            a1 += a[j0 + i] * wv;
            a2 += a[DD + j0 + i] * wv;
        }
        p1[g * 16 + l] = a1; p2[g * 16 + l] = a2;
        __syncthreads();
        if (tid < 32) {
            int half = tid >> 4, c = tid & 15;
            const float* ps = half ? p2 : p1;
            float s = 0.f;
#pragma unroll
            for (int r = 0; r < 32; r++) s += ps[r * 16 + c];
            g_w12[half * DD + blk * 16 + c] = s;
        }
    }
    gridbar(&g_b1);

    // ===== phase 1: p[i]=x[i].w1, q[i]=x[i].w2 (64 rows/block, x read once) ====
    {
        const float4* x4 = (const float4*)x;
        const float4* w4 = (const float4*)g_w12;
        float4 w1a = w4[lane * 2],      w1b = w4[lane * 2 + 1];
        float4 w2a = w4[64 + lane * 2], w2b = w4[64 + lane * 2 + 1];
        int rb = blk * 64 + wid * 4;
#pragma unroll
        for (int pp = 0; pp < 2; pp++) {   // two rows at a time: MLP 4
            int r0 = rb + pp * 2, r1 = r0 + 1;
            float4 xa0 = x4[r0 * 64 + lane * 2], xb0 = x4[r0 * 64 + lane * 2 + 1];
            float4 xa1 = x4[r1 * 64 + lane * 2], xb1 = x4[r1 * 64 + lane * 2 + 1];
            float p0 = dot4(xa0, w1a) + dot4(xb0, w1b);
            float q0 = dot4(xa0, w2a) + dot4(xb0, w2b);
            float p1 = dot4(xa1, w1a) + dot4(xb1, w1b);
            float q1 = dot4(xa1, w2a) + dot4(xb1, w2b);
#pragma unroll
            for (int o = 16; o; o >>= 1) {
                p0 += __shfl_xor_sync(0xFFFFFFFFu, p0, o);
                q0 += __shfl_xor_sync(0xFFFFFFFFu, q0, o);
                p1 += __shfl_xor_sync(0xFFFFFFFFu, p1, o);
                q1 += __shfl_xor_sync(0xFFFFFFFFu, q1, o);
            }
            if (lane == 0) { g_p[r0] = p0; g_q[r0] = q0; g_p[r1] = p1; g_q[r1] = q1; }
        }
    }
    gridbar(&g_b2);

    // ================= phase 2: scalar edge pass -> gather tables ===============
    {
        int e = blk * 64 + tid;
        if (tid < 64 && e < EE) {
            int g = gov[e], d = dep[e];
            float s = g_p[g] + g_q[d];
            float coef = (s > 0.f) ? 1.f : (1.f / (float)NN);
            g_cA[d] = 1.f;  g_sA[d] = g;   // h[dep]  = Hx[gov]
            g_cB[g] = coef; g_sB[g] = d;   // h[gov] += coef * Hx[dep]
        }
    }
    gridbar(&g_b3);

    // ================= phase 3: fused-gather tf32 GEMM (r14 body) ==============
    {
        float* Asm = sm;              // [2][128*36]
        float* Bsm = sm + 2 * TSTG;   // [2][128*36]
        int m0 = (blk >> 1) * 128;
        int n0 = (blk & 1) * 128;

        int arow = tid >> 2;
        int aq   = tid & 3;
        int row  = m0 + arow;
        float cA = g_cA[row], cB = g_cB[row];
        int   sA = g_sA[row], sB = g_sB[row];

        const float4* x4 = (const float4*)x;
        const float4* W4 = (const float4*)W;
        int aOff = sA * 64 + aq * 2;
        int bOff = sB * 64 + aq * 2;
        int wOff = (n0 + arow) * 64 + aq * 2;
        int st0  = arow * 36 + aq * 8;

        float4 rg[2], rb[2], rw[2];
#pragma unroll
        for (int j = 0; j < 2; j++) { rg[j] = x4[aOff + j]; rb[j] = x4[bOff + j]; rw[j] = W4[wOff + j]; }

#define STORE_TILE(buf) do {                                                  \
        float* Ad = Asm + (buf) * TSTG + st0;                                 \
        float* Bd = Bsm + (buf) * TSTG + st0;                                 \
        _Pragma("unroll")                                                     \
        for (int j = 0; j < 2; j++) {                                         \
            Ad[j*4+0] = tfbits(cA * rg[j].x + cB * rb[j].x);                  \
            Ad[j*4+1] = tfbits(cA * rg[j].y + cB * rb[j].y);                  \
            Ad[j*4+2] = tfbits(cA * rg[j].z + cB * rb[j].z);                  \
            Ad[j*4+3] = tfbits(cA * rg[j].w + cB * rb[j].w);                  \
            Bd[j*4+0] = tfbits(rw[j].x);                                      \
            Bd[j*4+1] = tfbits(rw[j].y);                                      \
            Bd[j*4+2] = tfbits(rw[j].z);                                      \
            Bd[j*4+3] = tfbits(rw[j].w);                                      \
        }                                                                     \
    } while (0)

        STORE_TILE(0);

        // fragments: 16 warps 4(m) x 4(n), warp tile 32x32
        int wm  = (wid & 3) * 32;
        int wn  = (wid >> 2) * 32;
        int aRow = wm + (lane & 7) + ((lane & 8) ? 8 : 0);
        int aColF = (lane & 16) ? 4 : 0;
        unsigned aB = su32(Asm + aRow * 36 + aColF);
        // B pair-load addressing: lanes 16-31 target the second n-frag (+8 rows)
        int bRow = wn + (lane & 7) + ((lane & 16) ? 8 : 0);
        int bColF = (lane & 8) ? 4 : 0;
        unsigned bB = su32(Bsm + bRow * 36 + bColF);

        float acc[2][4][4];
#pragma unroll
        for (int i = 0; i < 2; i++)
#pragma unroll
            for (int j = 0; j < 4; j++)
#pragma unroll
                for (int v = 0; v < 4; v++) acc[i][j][v] = 0.f;

        __syncthreads();

#pragma unroll 1
        for (int kt = 0; kt < 8; kt++) {
            if (kt < 7) {                    // prefetch next k-slab
                int kq = (kt + 1) * 8;
#pragma unroll
                for (int j = 0; j < 2; j++) {
                    rg[j] = x4[aOff + kq + j];
                    rb[j] = x4[bOff + kq + j];
                    rw[j] = W4[wOff + kq + j];
                }
            }
            int buf = kt & 1;
            unsigned aS = aB + buf * TSTG * 4;
            unsigned bS = bB + buf * TSTG * 4;
#pragma unroll
            for (int ks = 0; ks < 4; ks++) {
                int k = ks * 8;
                unsigned af[2][4], bf[4][2];
#pragma unroll
                for (int mf = 0; mf < 2; mf++)
                    asm volatile("ldmatrix.sync.aligned.m8n8.x4.shared.b16 {%0,%1,%2,%3}, [%4];"
                        : "=r"(af[mf][0]), "=r"(af[mf][1]), "=r"(af[mf][2]), "=r"(af[mf][3])
                        : "r"(aS + (unsigned)((mf * 576 + k) * 4)));
#pragma unroll
                for (int np = 0; np < 2; np++)   // one x4 = two n-frags
                    asm volatile("ldmatrix.sync.aligned.m8n8.x4.shared.b16 {%0,%1,%2,%3}, [%4];"
                        : "=r"(bf[np*2][0]), "=r"(bf[np*2][1]),
                          "=r"(bf[np*2+1][0]), "=r"(bf[np*2+1][1])
                        : "r"(bS + (unsigned)((np * 576 + k) * 4)));
#pragma unroll
                for (int mf = 0; mf < 2; mf++)
#pragma unroll
                    for (int nf = 0; nf < 4; nf++)
                        asm volatile(
                            "mma.sync.aligned.m16n8k8.row.col.f32.tf32.tf32.f32 "
                            "{%0,%1,%2,%3}, {%4,%5,%6,%7}, {%8,%9}, {%0,%1,%2,%3};"
                            : "+f"(acc[mf][nf][0]), "+f"(acc[mf][nf][1]),
                              "+f"(acc[mf][nf][2]), "+f"(acc[mf][nf][3])
                            : "r"(af[mf][0]), "r"(af[mf][1]), "r"(af[mf][2]), "r"(af[mf][3]),
                              "r"(bf[nf][0]), "r"(bf[nf][1]));
            }
            if (kt < 7) {
                STORE_TILE(1 - buf);
                __syncthreads();
            }
        }

        int er = m0 + wm + (lane >> 2);
        int ec = n0 + wn + (lane & 3) * 2;
#pragma unroll
        for (int mf = 0; mf < 2; mf++) {
#pragma unroll
            for (int nf = 0; nf < 4; nf++) {
                float2 v0, v1;
                v0.x = lrelu(acc[mf][nf][0]); v0.y = lrelu(acc[mf][nf][1]);
                v1.x = lrelu(acc[mf][nf][2]); v1.y = lrelu(acc[mf][nf][3]);
                *(float2*)&out[(er + mf * 16) * DD + ec + nf * 8]     = v0;
                *(float2*)&out[(er + mf * 16 + 8) * DD + ec + nf * 8] = v1;
            }
        }
    }

    // ---- reset barrier counters for next graph replay (last block does it) ----
    __syncthreads();
    if (tid == 0) {
        unsigned old = atomicAdd(&g_br, 1u);
        if (old == GRID - 1) {
            g_b1 = 0; g_b2 = 0; g_b3 = 0; g_br = 0;
            __threadfence();
        }
    }
}

// ---------------- launch ---------------------------------------------------------
extern "C" void kernel_launch(void* const* d_in, const int* in_sizes, int n_in,
                              void* d_out, int out_size) {
    const float* x   = (const float*)d_in[0];
    const float* W   = (const float*)d_in[1];
    const float* a   = (const float*)d_in[2];
    const int*   dep = (const int*)d_in[3];
    const int*   gov = (const int*)d_in[4];
    float* out = (float*)d_out;

    int smem = 4 * TSTG * 4;   // 73,728 B
    cudaFuncSetAttribute(k_fused, cudaFuncAttributeMaxDynamicSharedMemorySize, smem);

    k_fused<<<GRID, 512, smem>>>(x, W, a, dep, gov, out);
}

// round 16
// speedup vs baseline: 1.0089x; 1.0089x over previous
#include <cuda_runtime.h>

#define DD   256
#define NN   8192
#define EE   8191
#define ALPHA 0.2f
#define GRID 128

// ---------------- scratch (allocation-free __device__ globals, zero-init) -------
__device__ float g_w12[2 * DD];
// per-output-row gather tables: out_row r = lrelu((cA*x[sA] + cB*x[sB]) @ W^T)
__device__ float g_cA[NN];
__device__ float g_cB[NN];
__device__ int   g_sA[NN];
__device__ int   g_sB[NN];
__device__ unsigned g_bar1, g_bar2, g_bar3;   // self-resetting each call

__device__ __forceinline__ unsigned f2tf(float f) {
    unsigned r; asm("cvt.rna.tf32.f32 %0, %1;" : "=r"(r) : "f"(f)); return r;
}
__device__ __forceinline__ float tfbits(float f) { return __uint_as_float(f2tf(f)); }
__device__ __forceinline__ float lrelu(float v) { return v > 0.f ? v : ALPHA * v; }
__device__ __forceinline__ unsigned su32(const void* p) {
    return (unsigned)__cvta_generic_to_shared(p);
}
__device__ __forceinline__ float dot4(float4 a, float4 b) {
    return a.x * b.x + a.y * b.y + a.z * b.z + a.w * b.w;
}
__device__ __forceinline__ void gridbar(unsigned* ctr) {
    __syncthreads();
    if (threadIdx.x == 0) {
        __threadfence();
        atomicAdd(ctr, 1u);
        while (*(volatile unsigned*)ctr < GRID) __nanosleep(32);
        __threadfence();
    }
    __syncthreads();
}
// named barriers: FULL buf -> id 1+buf, EMPTY buf -> id 3+buf (id 0 = syncthreads)
__device__ __forceinline__ void nbar_sync(int id) {
    asm volatile("bar.sync %0, 512;" :: "r"(id) : "memory");
}
__device__ __forceinline__ void nbar_arrive(int id) {
    asm volatile("bar.arrive %0, 512;" :: "r"(id) : "memory");
}

#define TSTG (128 * 36)

__global__ __launch_bounds__(512, 1) void k_fused(
    const float* __restrict__ x, const float* __restrict__ W,
    const float* __restrict__ a,
    const int* __restrict__ dep, const int* __restrict__ gov,
    float* __restrict__ out)
{
    extern __shared__ float sm[];
    int tid = threadIdx.x;
    int blk = blockIdx.x;
    int wid = tid >> 5, lane = tid & 31;

    // ================= phase 0: w12 on blocks 0..15 =================
    if (blk < 16) {
        float* p1 = sm;            // [32][16]
        float* p2 = sm + 512;
        int l = tid & 15, g = tid >> 4;      // col-in-slice, j-group (0..31)
        int col = blk * 16 + l;
        int j0 = g * 8;
        float a1 = 0.f, a2 = 0.f;
#pragma unroll
        for (int i = 0; i < 8; i++) {
            float wv = W[(j0 + i) * DD + col];
            a1 += a[j0 + i] * wv;
            a2 += a[DD + j0 + i] * wv;
        }
        p1[g * 16 + l] = a1; p2[g * 16 + l] = a2;
        __syncthreads();
        if (tid < 32) {
            int half = tid >> 4, c = tid & 15;
            const float* ps = half ? p2 : p1;
            float s = 0.f;
#pragma unroll
            for (int r = 0; r < 32; r++) s += ps[r * 16 + c];
            g_w12[half * DD + blk * 16 + c] = s;
        }
    }
    gridbar(&g_bar1);

    // ================= phase 1: edges (2048 warps x 4, paired gathers) =========
    {
        int eb = (blk * 16 + wid) * 4;       // 0..8191
        const float4* x4 = (const float4*)x;
        const float4* w4 = (const float4*)g_w12;
        float4 w1a = w4[lane * 2],      w1b = w4[lane * 2 + 1];
        float4 w2a = w4[64 + lane * 2], w2b = w4[64 + lane * 2 + 1];
        int ge[4], de[4];
#pragma unroll
        for (int i = 0; i < 4; i++) {
            int e = eb + i;
            ge[i] = (e < EE) ? gov[e] : 0;
            de[i] = (e < EE) ? dep[e] : 0;
        }
#pragma unroll
        for (int p = 0; p < 2; p++) {        // two edges at a time: MLP 8
            int i0 = p * 2, i1 = p * 2 + 1;
            float4 ag0 = x4[ge[i0] * 64 + lane * 2], ag1 = x4[ge[i0] * 64 + lane * 2 + 1];
            float4 ad0 = x4[de[i0] * 64 + lane * 2], ad1 = x4[de[i0] * 64 + lane * 2 + 1];
            float4 bg0 = x4[ge[i1] * 64 + lane * 2], bg1 = x4[ge[i1] * 64 + lane * 2 + 1];
            float4 bd0 = x4[de[i1] * 64 + lane * 2], bd1 = x4[de[i1] * 64 + lane * 2 + 1];
            float s0 = dot4(ag0, w1a) + dot4(ag1, w1b) + dot4(ad0, w2a) + dot4(ad1, w2b);
            float s1 = dot4(bg0, w1a) + dot4(bg1, w1b) + dot4(bd0, w2a) + dot4(bd1, w2b);
#pragma unroll
            for (int o = 16; o; o >>= 1) {
                s0 += __shfl_xor_sync(0xFFFFFFFFu, s0, o);
                s1 += __shfl_xor_sync(0xFFFFFFFFu, s1, o);
            }
            if (lane == 0 && eb + i0 < EE) {
                float c0 = (s0 > 0.f) ? 1.f : (1.f / (float)NN);
                g_cA[de[i0]] = 1.f; g_sA[de[i0]] = ge[i0];
                g_cB[ge[i0]] = c0;  g_sB[ge[i0]] = de[i0];
            }
            if (lane == 0 && eb + i1 < EE) {
                float c1 = (s1 > 0.f) ? 1.f : (1.f / (float)NN);
                g_cA[de[i1]] = 1.f; g_sA[de[i1]] = ge[i1];
                g_cB[ge[i1]] = c1;  g_sB[ge[i1]] = de[i1];
            }
        }
    }
    gridbar(&g_bar2);

    // ========== phase 2: warp-specialized fused-gather tf32 GEMM ==============
    // warps 0-7: consumers (2m x 4n, warp tile 64x32); warps 8-15: producers
    {
        float* Asm = sm;              // [2][128*36]
        float* Bsm = sm + 2 * TSTG;   // [2][128*36]
        int m0 = (blk >> 1) * 128;
        int n0 = (blk & 1) * 128;

        if (wid >= 8) {
            // ---------------- producer ----------------
            int ptid = tid - 256;
            int row  = ptid >> 1;          // 0..127
            int half = ptid & 1;           // 16-float half of the 32-k slab
            int grow = m0 + row;
            float cA = g_cA[grow], cB = g_cB[grow];
            int   sA = g_sA[grow], sB = g_sB[grow];

            const float4* x4 = (const float4*)x;
            const float4* W4 = (const float4*)W;
            int aOff = sA * 64 + half * 4;
            int bOff = sB * 64 + half * 4;
            int wOff = (n0 + row) * 64 + half * 4;
            int st0  = row * 36 + half * 16;

            float4 rg[4], rb[4], rw[4];
#pragma unroll
            for (int j = 0; j < 4; j++) {
                rg[j] = x4[aOff + j]; rb[j] = x4[bOff + j]; rw[j] = W4[wOff + j];
            }

#pragma unroll 1
            for (int kt = 0; kt < 8; kt++) {
                int buf = kt & 1;
                if (kt >= 2) nbar_sync(3 + buf);        // wait consumers done with buf
                float* Ad = Asm + buf * TSTG + st0;
                float* Bd = Bsm + buf * TSTG + st0;
#pragma unroll
                for (int j = 0; j < 4; j++) {
                    Ad[j*4+0] = tfbits(cA * rg[j].x + cB * rb[j].x);
                    Ad[j*4+1] = tfbits(cA * rg[j].y + cB * rb[j].y);
                    Ad[j*4+2] = tfbits(cA * rg[j].z + cB * rb[j].z);
                    Ad[j*4+3] = tfbits(cA * rg[j].w + cB * rb[j].w);
                    Bd[j*4+0] = tfbits(rw[j].x);
                    Bd[j*4+1] = tfbits(rw[j].y);
                    Bd[j*4+2] = tfbits(rw[j].z);
                    Bd[j*4+3] = tfbits(rw[j].w);
                }
                nbar_arrive(1 + buf);                   // publish buf
                if (kt < 7) {                           // prefetch next slab
                    int kq = (kt + 1) * 8;
#pragma unroll
                    for (int j = 0; j < 4; j++) {
                        rg[j] = x4[aOff + kq + j];
                        rb[j] = x4[bOff + kq + j];
                        rw[j] = W4[wOff + kq + j];
                    }
                }
            }
        } else {
            // ---------------- consumer ----------------
            int wm = (wid & 1) * 64;       // 2 m-groups, warp covers 64 rows
            int wn = (wid >> 1) * 32;      // 4 n-groups, warp covers 32 cols
            int aRow = wm + (lane & 7) + ((lane & 8) ? 8 : 0);
            int aColF = (lane & 16) ? 4 : 0;
            unsigned aB = su32(Asm + aRow * 36 + aColF);
            int bRow = wn + (lane & 7) + ((lane & 16) ? 8 : 0);
            int bColF = (lane & 8) ? 4 : 0;
            unsigned bB = su32(Bsm + bRow * 36 + bColF);

            float acc[4][4][4];
#pragma unroll
            for (int i = 0; i < 4; i++)
#pragma unroll
                for (int j = 0; j < 4; j++)
#pragma unroll
                    for (int v = 0; v < 4; v++) acc[i][j][v] = 0.f;

#pragma unroll 1
            for (int kt = 0; kt < 8; kt++) {
                int buf = kt & 1;
                nbar_sync(1 + buf);                     // wait buf full
                unsigned aS = aB + buf * TSTG * 4;
                unsigned bS = bB + buf * TSTG * 4;
#pragma unroll
                for (int ks = 0; ks < 4; ks++) {
                    int k = ks * 8;
                    unsigned af[4][4], bf[4][2];
#pragma unroll
                    for (int mf = 0; mf < 4; mf++)
                        asm volatile("ldmatrix.sync.aligned.m8n8.x4.shared.b16 {%0,%1,%2,%3}, [%4];"
                            : "=r"(af[mf][0]), "=r"(af[mf][1]), "=r"(af[mf][2]), "=r"(af[mf][3])
                            : "r"(aS + (unsigned)((mf * 576 + k) * 4)));
#pragma unroll
                    for (int np = 0; np < 2; np++)      // one x4 = two n-frags
                        asm volatile("ldmatrix.sync.aligned.m8n8.x4.shared.b16 {%0,%1,%2,%3}, [%4];"
                            : "=r"(bf[np*2][0]), "=r"(bf[np*2][1]),
                              "=r"(bf[np*2+1][0]), "=r"(bf[np*2+1][1])
                            : "r"(bS + (unsigned)((np * 576 + k) * 4)));
#pragma unroll
                    for (int mf = 0; mf < 4; mf++)
#pragma unroll
                        for (int nf = 0; nf < 4; nf++)
                            asm volatile(
                                "mma.sync.aligned.m16n8k8.row.col.f32.tf32.tf32.f32 "
                                "{%0,%1,%2,%3}, {%4,%5,%6,%7}, {%8,%9}, {%0,%1,%2,%3};"
                                : "+f"(acc[mf][nf][0]), "+f"(acc[mf][nf][1]),
                                  "+f"(acc[mf][nf][2]), "+f"(acc[mf][nf][3])
                                : "r"(af[mf][0]), "r"(af[mf][1]), "r"(af[mf][2]), "r"(af[mf][3]),
                                  "r"(bf[nf][0]), "r"(bf[nf][1]));
                }
                if (kt < 6) nbar_arrive(3 + buf);       // release buf to producers
            }

            // epilogue: leaky relu, float2 stores
            int er = m0 + wm + (lane >> 2);
            int ec = n0 + wn + (lane & 3) * 2;
#pragma unroll
            for (int mf = 0; mf < 4; mf++) {
#pragma unroll
                for (int nf = 0; nf < 4; nf++) {
                    float2 v0, v1;
                    v0.x = lrelu(acc[mf][nf][0]); v0.y = lrelu(acc[mf][nf][1]);
                    v1.x = lrelu(acc[mf][nf][2]); v1.y = lrelu(acc[mf][nf][3]);
                    *(float2*)&out[(er + mf * 16) * DD + ec + nf * 8]     = v0;
                    *(float2*)&out[(er + mf * 16 + 8) * DD + ec + nf * 8] = v1;
                }
            }
        }
    }

    // ---- reset barrier counters for next graph replay (last block does it) ----
    __syncthreads();
    if (tid == 0) {
        unsigned old = atomicAdd(&g_bar3, 1u);
        if (old == GRID - 1) {
            g_bar1 = 0; g_bar2 = 0; g_bar3 = 0;
            __threadfence();
        }
    }
}

// ---------------- launch ---------------------------------------------------------
extern "C" void kernel_launch(void* const* d_in, const int* in_sizes, int n_in,
                              void* d_out, int out_size) {
    const float* x   = (const float*)d_in[0];
    const float* W   = (const float*)d_in[1];
    const float* a   = (const float*)d_in[2];
    const int*   dep = (const int*)d_in[3];
    const int*   gov = (const int*)d_in[4];
    float* out = (float*)d_out;

    int smem = 4 * TSTG * 4;   // 73,728 B
    cudaFuncSetAttribute(k_fused, cudaFuncAttributeMaxDynamicSharedMemorySize, smem);

    k_fused<<<GRID, 512, smem>>>(x, W, a, dep, gov, out);
}

// round 17
// speedup vs baseline: 1.0986x; 1.0889x over previous
#include <cuda_runtime.h>

#define DD   256
#define NN   8192
#define EE   8191
#define ALPHA 0.2f
#define GRID 128

// ---------------- scratch (allocation-free __device__ globals, zero-init) -------
__device__ float g_w12[2 * DD];
// per-output-row gather tables: out_row r = lrelu((cA*x[sA] + cB*x[sB]) @ W^T)
__device__ float g_cA[NN];
__device__ float g_cB[NN];
__device__ int   g_sA[NN];
__device__ int   g_sB[NN];
__device__ unsigned g_bar1, g_bar2, g_bar3;   // self-resetting each call

__device__ __forceinline__ unsigned f2tf(float f) {
    unsigned r; asm("cvt.rna.tf32.f32 %0, %1;" : "=r"(r) : "f"(f)); return r;
}
__device__ __forceinline__ float tfbits(float f) { return __uint_as_float(f2tf(f)); }
__device__ __forceinline__ float lrelu(float v) { return v > 0.f ? v : ALPHA * v; }
__device__ __forceinline__ unsigned su32(const void* p) {
    return (unsigned)__cvta_generic_to_shared(p);
}
__device__ __forceinline__ float dot4(float4 a, float4 b) {
    return a.x * b.x + a.y * b.y + a.z * b.z + a.w * b.w;
}
__device__ __forceinline__ void gridbar(unsigned* ctr) {
    __syncthreads();
    if (threadIdx.x == 0) {
        __threadfence();
        atomicAdd(ctr, 1u);
        while (*(volatile unsigned*)ctr < GRID) __nanosleep(32);
        __threadfence();
    }
    __syncthreads();
}

#define TSTG (128 * 36)

__global__ __launch_bounds__(512, 1) void k_fused(
    const float* __restrict__ x, const float* __restrict__ W,
    const float* __restrict__ a,
    const int* __restrict__ dep, const int* __restrict__ gov,
    float* __restrict__ out)
{
    extern __shared__ float sm[];
    int tid = threadIdx.x;
    int blk = blockIdx.x;
    int wid = tid >> 5, lane = tid & 31;

    // ---- edge assignment (phase 1): 4 edges per warp, loads hoistable ----
    const float4* x4g = (const float4*)x;
    int eb = (blk * 16 + wid) * 4;       // 0..8191
    int ge[4], de[4];
    float4 xr[16];

#define LOAD_EDGES() do {                                                     \
        _Pragma("unroll")                                                     \
        for (int i = 0; i < 4; i++) {                                         \
            int e = eb + i;                                                   \
            ge[i] = (e < EE) ? gov[e] : 0;                                    \
            de[i] = (e < EE) ? dep[e] : 0;                                    \
        }                                                                     \
        _Pragma("unroll")                                                     \
        for (int i = 0; i < 4; i++) {                                         \
            xr[i*4+0] = x4g[ge[i] * 64 + lane * 2];                           \
            xr[i*4+1] = x4g[ge[i] * 64 + lane * 2 + 1];                       \
            xr[i*4+2] = x4g[de[i] * 64 + lane * 2];                           \
            xr[i*4+3] = x4g[de[i] * 64 + lane * 2 + 1];                       \
        }                                                                     \
    } while (0)

    // ================= phase 0: w12 on blocks 0..15; others hoist gathers ======
    if (blk < 16) {
        float* p1 = sm;            // [32][16]
        float* p2 = sm + 512;
        int l = tid & 15, g = tid >> 4;      // col-in-slice, j-group (0..31)
        int col = blk * 16 + l;
        int j0 = g * 8;
        float a1 = 0.f, a2 = 0.f;
#pragma unroll
        for (int i = 0; i < 8; i++) {
            float wv = W[(j0 + i) * DD + col];
            a1 += a[j0 + i] * wv;
            a2 += a[DD + j0 + i] * wv;
        }
        p1[g * 16 + l] = a1; p2[g * 16 + l] = a2;
        __syncthreads();
        if (tid < 32) {
            int half = tid >> 4, c = tid & 15;
            const float* ps = half ? p2 : p1;
            float s = 0.f;
#pragma unroll
            for (int r = 0; r < 32; r++) s += ps[r * 16 + c];
            g_w12[half * DD + blk * 16 + c] = s;
        }
    } else {
        LOAD_EDGES();              // overlap gather latency with w12 compute
    }
    gridbar(&g_bar1);

    // ================= phase 1: logits + gather tables =========================
    {
        if (blk < 16) LOAD_EDGES();

        const float4* w4 = (const float4*)g_w12;
        float4 w1a = w4[lane * 2],      w1b = w4[lane * 2 + 1];
        float4 w2a = w4[64 + lane * 2], w2b = w4[64 + lane * 2 + 1];

        float s0 = dot4(xr[0],  w1a) + dot4(xr[1],  w1b) + dot4(xr[2],  w2a) + dot4(xr[3],  w2b);
        float s1 = dot4(xr[4],  w1a) + dot4(xr[5],  w1b) + dot4(xr[6],  w2a) + dot4(xr[7],  w2b);
        float s2 = dot4(xr[8],  w1a) + dot4(xr[9],  w1b) + dot4(xr[10], w2a) + dot4(xr[11], w2b);
        float s3 = dot4(xr[12], w1a) + dot4(xr[13], w1b) + dot4(xr[14], w2a) + dot4(xr[15], w2b);
#pragma unroll
        for (int o = 16; o; o >>= 1) {
            s0 += __shfl_xor_sync(0xFFFFFFFFu, s0, o);
            s1 += __shfl_xor_sync(0xFFFFFFFFu, s1, o);
            s2 += __shfl_xor_sync(0xFFFFFFFFu, s2, o);
            s3 += __shfl_xor_sync(0xFFFFFFFFu, s3, o);
        }
        if (lane == 0) {
            float sv[4] = {s0, s1, s2, s3};
#pragma unroll
            for (int i = 0; i < 4; i++) {
                if (eb + i < EE) {
                    float coef = (sv[i] > 0.f) ? 1.f : (1.f / (float)NN);
                    g_cA[de[i]] = 1.f;  g_sA[de[i]] = ge[i];   // h[dep]  = Hx[gov]
                    g_cB[ge[i]] = coef; g_sB[ge[i]] = de[i];   // h[gov] += coef*Hx[dep]
                }
            }
        }
    }
    gridbar(&g_bar2);

    // ================= phase 2: fused-gather tf32 GEMM (r14 body) ==============
    {
        float* Asm = sm;              // [2][128*36]
        float* Bsm = sm + 2 * TSTG;   // [2][128*36]
        int m0 = (blk >> 1) * 128;
        int n0 = (blk & 1) * 128;

        int arow = tid >> 2;
        int aq   = tid & 3;
        int row  = m0 + arow;
        float cA = g_cA[row], cB = g_cB[row];
        int   sA = g_sA[row], sB = g_sB[row];

        const float4* x4 = (const float4*)x;
        const float4* W4 = (const float4*)W;
        int aOff = sA * 64 + aq * 2;
        int bOff = sB * 64 + aq * 2;
        int wOff = (n0 + arow) * 64 + aq * 2;
        int st0  = arow * 36 + aq * 8;

        float4 rg[2], rb[2], rw[2];
#pragma unroll
        for (int j = 0; j < 2; j++) { rg[j] = x4[aOff + j]; rb[j] = x4[bOff + j]; rw[j] = W4[wOff + j]; }

#define STORE_TILE(buf) do {                                                  \
        float* Ad = Asm + (buf) * TSTG + st0;                                 \
        float* Bd = Bsm + (buf) * TSTG + st0;                                 \
        _Pragma("unroll")                                                     \
        for (int j = 0; j < 2; j++) {                                         \
            Ad[j*4+0] = tfbits(cA * rg[j].x + cB * rb[j].x);                  \
            Ad[j*4+1] = tfbits(cA * rg[j].y + cB * rb[j].y);                  \
            Ad[j*4+2] = tfbits(cA * rg[j].z + cB * rb[j].z);                  \
            Ad[j*4+3] = tfbits(cA * rg[j].w + cB * rb[j].w);                  \
            Bd[j*4+0] = tfbits(rw[j].x);                                      \
            Bd[j*4+1] = tfbits(rw[j].y);                                      \
            Bd[j*4+2] = tfbits(rw[j].z);                                      \
            Bd[j*4+3] = tfbits(rw[j].w);                                      \
        }                                                                     \
    } while (0)

        STORE_TILE(0);

        // fragments: 16 warps 4(m) x 4(n), warp tile 32x32
        int wm  = (wid & 3) * 32;
        int wn  = (wid >> 2) * 32;
        int aRow = wm + (lane & 7) + ((lane & 8) ? 8 : 0);
        int aColF = (lane & 16) ? 4 : 0;
        unsigned aB = su32(Asm + aRow * 36 + aColF);
        // B pair-load addressing: lanes 16-31 target the second n-frag (+8 rows)
        int bRow = wn + (lane & 7) + ((lane & 16) ? 8 : 0);
        int bColF = (lane & 8) ? 4 : 0;
        unsigned bB = su32(Bsm + bRow * 36 + bColF);

        float acc[2][4][4];
#pragma unroll
        for (int i = 0; i < 2; i++)
#pragma unroll
            for (int j = 0; j < 4; j++)
#pragma unroll
                for (int v = 0; v < 4; v++) acc[i][j][v] = 0.f;

        __syncthreads();

#pragma unroll 1
        for (int kt = 0; kt < 8; kt++) {
            if (kt < 7) {                    // prefetch next k-slab
                int kq = (kt + 1) * 8;
#pragma unroll
                for (int j = 0; j < 2; j++) {
                    rg[j] = x4[aOff + kq + j];
                    rb[j] = x4[bOff + kq + j];
                    rw[j] = W4[wOff + kq + j];
                }
            }
            int buf = kt & 1;
            unsigned aS = aB + buf * TSTG * 4;
            unsigned bS = bB + buf * TSTG * 4;
#pragma unroll
            for (int ks = 0; ks < 4; ks++) {
                int k = ks * 8;
                unsigned af[2][4], bf[4][2];
#pragma unroll
                for (int mf = 0; mf < 2; mf++)
                    asm volatile("ldmatrix.sync.aligned.m8n8.x4.shared.b16 {%0,%1,%2,%3}, [%4];"
                        : "=r"(af[mf][0]), "=r"(af[mf][1]), "=r"(af[mf][2]), "=r"(af[mf][3])
                        : "r"(aS + (unsigned)((mf * 576 + k) * 4)));
#pragma unroll
                for (int np = 0; np < 2; np++)   // one x4 = two n-frags
                    asm volatile("ldmatrix.sync.aligned.m8n8.x4.shared.b16 {%0,%1,%2,%3}, [%4];"
                        : "=r"(bf[np*2][0]), "=r"(bf[np*2][1]),
                          "=r"(bf[np*2+1][0]), "=r"(bf[np*2+1][1])
                        : "r"(bS + (unsigned)((np * 576 + k) * 4)));
#pragma unroll
                for (int mf = 0; mf < 2; mf++)
#pragma unroll
                    for (int nf = 0; nf < 4; nf++)
                        asm volatile(
                            "mma.sync.aligned.m16n8k8.row.col.f32.tf32.tf32.f32 "
                            "{%0,%1,%2,%3}, {%4,%5,%6,%7}, {%8,%9}, {%0,%1,%2,%3};"
                            : "+f"(acc[mf][nf][0]), "+f"(acc[mf][nf][1]),
                              "+f"(acc[mf][nf][2]), "+f"(acc[mf][nf][3])
                            : "r"(af[mf][0]), "r"(af[mf][1]), "r"(af[mf][2]), "r"(af[mf][3]),
                              "r"(bf[nf][0]), "r"(bf[nf][1]));
            }
            if (kt < 7) {
                STORE_TILE(1 - buf);
                __syncthreads();
            }
        }

        int er = m0 + wm + (lane >> 2);
        int ec = n0 + wn + (lane & 3) * 2;
#pragma unroll
        for (int mf = 0; mf < 2; mf++) {
#pragma unroll
            for (int nf = 0; nf < 4; nf++) {
                float2 v0, v1;
                v0.x = lrelu(acc[mf][nf][0]); v0.y = lrelu(acc[mf][nf][1]);
                v1.x = lrelu(acc[mf][nf][2]); v1.y = lrelu(acc[mf][nf][3]);
                *(float2*)&out[(er + mf * 16) * DD + ec + nf * 8]     = v0;
                *(float2*)&out[(er + mf * 16 + 8) * DD + ec + nf * 8] = v1;
            }
        }
    }

    // ---- reset barrier counters for next graph replay (last block does it) ----
    __syncthreads();
    if (tid == 0) {
        unsigned old = atomicAdd(&g_bar3, 1u);
        if (old == GRID - 1) {
            g_bar1 = 0; g_bar2 = 0; g_bar3 = 0;
            __threadfence();
        }
    }
}

// ---------------- launch ---------------------------------------------------------
extern "C" void kernel_launch(void* const* d_in, const int* in_sizes, int n_in,
                              void* d_out, int out_size) {
    const float* x   = (const float*)d_in[0];
    const float* W   = (const float*)d_in[1];
    const float* a   = (const float*)d_in[2];
    const int*   dep = (const int*)d_in[3];
    const int*   gov = (const int*)d_in[4];
    float* out = (float*)d_out;

    int smem = 4 * TSTG * 4;   // 73,728 B
    cudaFuncSetAttribute(k_fused, cudaFuncAttributeMaxDynamicSharedMemorySize, smem);

    k_fused<<<GRID, 512, smem>>>(x, W, a, dep, gov, out);
}